// round 1
// baseline (speedup 1.0000x reference)
#include <cuda_runtime.h>
#include <math.h>

#define NLAYER 12
#define NH 12
#define DH 64
#define DMODEL 768
#define DFF 3072
#define NV 10000
#define QLEN 512
#define MLEN 512
#define CLEN 32
#define BSZ 4
#define KLEN 1056               // CLEN + MLEN + QLEN
#define QB (QLEN*BSZ)           // 2048
#define KB (KLEN*BSZ)           // 4224
#define TND (3*NH*DH)           // 2304
#define ND (NH*DH)              // 768
#define NBATCH (BSZ*NH)         // 48

// ---------------- scratch (device globals; no allocation) ----------------
__device__ float g_h[QB*DMODEL];
__device__ float g_r[KLEN*DMODEL];
__device__ float g_heads[(size_t)KB*TND];
__device__ float g_rk[KLEN*DMODEL];
__device__ float g_ac[(size_t)NBATCH*QLEN*KLEN];
__device__ float g_bd[(size_t)NBATCH*QLEN*KLEN];
__device__ float g_av[QB*DMODEL];
__device__ float g_ff[(size_t)QB*DFF];

// ---------------- small helpers ----------------
__device__ __forceinline__ float warp_sum(float v) {
    #pragma unroll
    for (int o = 16; o; o >>= 1) v += __shfl_xor_sync(0xffffffffu, v, o);
    return v;
}
__device__ __forceinline__ float warp_max(float v) {
    #pragma unroll
    for (int o = 16; o; o >>= 1) v = fmaxf(v, __shfl_xor_sync(0xffffffffu, v, o));
    return v;
}
// block (256 threads) reduce-sum; red must be shared float[8]
__device__ __forceinline__ float block_sum(float v, float* red) {
    v = warp_sum(v);
    __syncthreads();
    if ((threadIdx.x & 31) == 0) red[threadIdx.x >> 5] = v;
    __syncthreads();
    float r = 0.f;
    #pragma unroll
    for (int k = 0; k < 8; k++) r += red[k];
    return r;
}

// ---------------- embedding ----------------
__global__ void embed_kernel(const int* __restrict__ x, const float* __restrict__ emb) {
    int idx = blockIdx.x * 256 + threadIdx.x;
    if (idx >= QB * DMODEL) return;
    int row = idx / DMODEL, d = idx % DMODEL;
    int tok = x[row];
    g_h[idx] = emb[(size_t)tok * DMODEL + d] * sqrtf(768.0f);
}

// ---------------- sinusoidal relative position embedding ----------------
__global__ void posemb_kernel() {
    int idx = blockIdx.x * 256 + threadIdx.x;
    if (idx >= KLEN * DMODEL) return;
    int p = idx / DMODEL, d = idx % DMODEL;
    float pos = (float)(KLEN - 1 - p);
    int dd = (d < 384) ? d : d - 384;
    float inv = 1.0f / powf(10000.0f, (float)(2 * dd) / 768.0f);
    float s = pos * inv;
    g_r[idx] = (d < 384) ? sinf(s) : cosf(s);
}

// ---------------- generic NN GEMM: C[M,N] = A[M,K] @ B[K,N] (+bias)(+relu) ----------------
__global__ void __launch_bounds__(256)
gemm_nn(const float* __restrict__ A, int lda,
        const float* __restrict__ B, int ldb,
        float* __restrict__ C, int ldc,
        int M, int N, int K,
        const float* __restrict__ bias, int relu)
{
    __shared__ float As[16][65];
    __shared__ float Bs[16][65];
    int tx = threadIdx.x & 15, ty = threadIdx.x >> 4;
    int row0 = blockIdx.y * 64, col0 = blockIdx.x * 64;
    float acc[4][4] = {};
    for (int k0 = 0; k0 < K; k0 += 16) {
        for (int idx = threadIdx.x; idx < 1024; idx += 256) {
            int m = idx >> 4, k = idx & 15;
            float v = 0.f;
            if (row0 + m < M) v = A[(size_t)(row0 + m) * lda + k0 + k];
            As[k][m] = v;
        }
        for (int idx = threadIdx.x; idx < 1024; idx += 256) {
            int k = idx >> 6, n = idx & 63;
            float v = 0.f;
            if (col0 + n < N) v = B[(size_t)(k0 + k) * ldb + col0 + n];
            Bs[k][n] = v;
        }
        __syncthreads();
        #pragma unroll
        for (int k = 0; k < 16; k++) {
            float a[4], b[4];
            #pragma unroll
            for (int u = 0; u < 4; u++) a[u] = As[k][ty * 4 + u];
            #pragma unroll
            for (int u = 0; u < 4; u++) b[u] = Bs[k][tx * 4 + u];
            #pragma unroll
            for (int i = 0; i < 4; i++)
                #pragma unroll
                for (int j = 0; j < 4; j++) acc[i][j] += a[i] * b[j];
        }
        __syncthreads();
    }
    #pragma unroll
    for (int i = 0; i < 4; i++) {
        int r = row0 + ty * 4 + i;
        if (r >= M) continue;
        #pragma unroll
        for (int j = 0; j < 4; j++) {
            int c = col0 + tx * 4 + j;
            if (c >= N) continue;
            float v = acc[i][j];
            if (bias) v += bias[c];
            if (relu) v = fmaxf(v, 0.f);
            C[(size_t)r * ldc + c] = v;
        }
    }
}

// ---------------- batched NT GEMM over (b,n): C[z,i,j] = sum_d (A[i,d]+bias[d]) * B[j,d] ----------------
__global__ void __launch_bounds__(256)
gemm_nt_batched(const float* __restrict__ A, int lda, int sAb, int sAn,
                const float* __restrict__ Abias,
                const float* __restrict__ B, int ldb, int sBb, int sBn,
                float* __restrict__ C,
                int M, int N, int K)
{
    int z = blockIdx.z, bb = z / NH, nn = z % NH;
    const float* Az = A + (size_t)bb * sAb + (size_t)nn * sAn;
    const float* Bz = B + (size_t)bb * sBb + (size_t)nn * sBn;
    float* Cz = C + (size_t)z * M * N;
    const float* bias = Abias + nn * DH;
    __shared__ float As[16][65];
    __shared__ float Bs[16][65];
    int tx = threadIdx.x & 15, ty = threadIdx.x >> 4;
    int row0 = blockIdx.y * 64, col0 = blockIdx.x * 64;
    float acc[4][4] = {};
    for (int k0 = 0; k0 < K; k0 += 16) {
        for (int idx = threadIdx.x; idx < 1024; idx += 256) {
            int m = idx >> 4, k = idx & 15;
            float v = 0.f;
            if (row0 + m < M) v = Az[(size_t)(row0 + m) * lda + k0 + k] + bias[k0 + k];
            As[k][m] = v;
        }
        for (int idx = threadIdx.x; idx < 1024; idx += 256) {
            int j = idx >> 4, k = idx & 15;
            float v = 0.f;
            if (col0 + j < N) v = Bz[(size_t)(col0 + j) * ldb + k0 + k];
            Bs[k][j] = v;
        }
        __syncthreads();
        #pragma unroll
        for (int k = 0; k < 16; k++) {
            float a[4], b[4];
            #pragma unroll
            for (int u = 0; u < 4; u++) a[u] = As[k][ty * 4 + u];
            #pragma unroll
            for (int u = 0; u < 4; u++) b[u] = Bs[k][tx * 4 + u];
            #pragma unroll
            for (int i = 0; i < 4; i++)
                #pragma unroll
                for (int j = 0; j < 4; j++) acc[i][j] += a[i] * b[j];
        }
        __syncthreads();
    }
    #pragma unroll
    for (int i = 0; i < 4; i++) {
        int r = row0 + ty * 4 + i;
        if (r >= M) continue;
        #pragma unroll
        for (int j = 0; j < 4; j++) {
            int c = col0 + tx * 4 + j;
            if (c >= N) continue;
            Cz[(size_t)r * N + c] = acc[i][j];
        }
    }
}

// ---------------- batched NN GEMM over (b,n): av = prob @ v ----------------
__global__ void __launch_bounds__(256)
gemm_nn_batched(const float* __restrict__ A, int lda, int sAz,
                const float* __restrict__ B, int ldb, int sBb, int sBn,
                float* __restrict__ C, int ldc, int sCb, int sCn,
                int M, int N, int K)
{
    int z = blockIdx.z, bb = z / NH, nn = z % NH;
    const float* Az = A + (size_t)z * sAz;
    const float* Bz = B + (size_t)bb * sBb + (size_t)nn * sBn;
    float* Cz = C + (size_t)bb * sCb + (size_t)nn * sCn;
    __shared__ float As[16][65];
    __shared__ float Bs[16][65];
    int tx = threadIdx.x & 15, ty = threadIdx.x >> 4;
    int row0 = blockIdx.y * 64, col0 = blockIdx.x * 64;
    float acc[4][4] = {};
    for (int k0 = 0; k0 < K; k0 += 16) {
        for (int idx = threadIdx.x; idx < 1024; idx += 256) {
            int m = idx >> 4, k = idx & 15;
            float v = 0.f;
            if (row0 + m < M) v = Az[(size_t)(row0 + m) * lda + k0 + k];
            As[k][m] = v;
        }
        for (int idx = threadIdx.x; idx < 1024; idx += 256) {
            int k = idx >> 6, n = idx & 63;
            float v = 0.f;
            if (col0 + n < N) v = Bz[(size_t)(k0 + k) * ldb + col0 + n];
            Bs[k][n] = v;
        }
        __syncthreads();
        #pragma unroll
        for (int k = 0; k < 16; k++) {
            float a[4], b[4];
            #pragma unroll
            for (int u = 0; u < 4; u++) a[u] = As[k][ty * 4 + u];
            #pragma unroll
            for (int u = 0; u < 4; u++) b[u] = Bs[k][tx * 4 + u];
            #pragma unroll
            for (int i = 0; i < 4; i++)
                #pragma unroll
                for (int j = 0; j < 4; j++) acc[i][j] += a[i] * b[j];
        }
        __syncthreads();
    }
    #pragma unroll
    for (int i = 0; i < 4; i++) {
        int r = row0 + ty * 4 + i;
        if (r >= M) continue;
        #pragma unroll
        for (int j = 0; j < 4; j++) {
            int c = col0 + tx * 4 + j;
            if (c >= N) continue;
            Cz[(size_t)r * ldc + c] = acc[i][j];
        }
    }
}

// ---------------- masked softmax with rel-shift folded in ----------------
// score[z,i,j] = (AC[z,i,j] + BD_raw[z,i, j + QLEN-1 - i]) / 8 for j <= i+CLEN+MLEN, else masked.
// prob written back into g_ac; masked entries -> 0.
__global__ void __launch_bounds__(256) softmax_kernel() {
    int i = blockIdx.x, z = blockIdx.y;
    float* row = g_ac + ((size_t)z * QLEN + i) * KLEN;
    const float* bdrow = g_bd + ((size_t)z * QLEN + i) * KLEN;
    int jmax = i + CLEN + MLEN;      // inclusive
    __shared__ float s[KLEN];
    __shared__ float red[8];
    int tid = threadIdx.x;
    float lmax = -3.0e38f;
    for (int j = tid; j <= jmax; j += 256) {
        float v = (row[j] + bdrow[j + QLEN - 1 - i]) * 0.125f;
        s[j] = v;
        lmax = fmaxf(lmax, v);
    }
    lmax = warp_max(lmax);
    __syncthreads();
    if ((tid & 31) == 0) red[tid >> 5] = lmax;
    __syncthreads();
    float m = red[0];
    #pragma unroll
    for (int k = 1; k < 8; k++) m = fmaxf(m, red[k]);
    float lsum = 0.f;
    for (int j = tid; j <= jmax; j += 256) {
        float e = expf(s[j] - m);
        s[j] = e;
        lsum += e;
    }
    float total = block_sum(lsum, red);
    float inv = 1.0f / total;
    __syncthreads();
    for (int j = tid; j < KLEN; j += 256)
        row[j] = (j <= jmax) ? s[j] * inv : 0.0f;
}

// ---------------- h = LayerNorm(h + res) * g + b ----------------
__global__ void __launch_bounds__(256)
add_ln_kernel(float* __restrict__ h, const float* __restrict__ res,
              const float* __restrict__ g, const float* __restrict__ b)
{
    __shared__ float red[8];
    int row = blockIdx.x, tid = threadIdx.x;
    size_t base = (size_t)row * DMODEL;
    float x0 = h[base + tid]       + res[base + tid];
    float x1 = h[base + tid + 256] + res[base + tid + 256];
    float x2 = h[base + tid + 512] + res[base + tid + 512];
    float S = block_sum(x0 + x1 + x2, red);
    float mean = S * (1.0f / 768.0f);
    float d0 = x0 - mean, d1 = x1 - mean, d2 = x2 - mean;
    float V = block_sum(d0 * d0 + d1 * d1 + d2 * d2, red);
    float inv = rsqrtf(V * (1.0f / 768.0f) + 1e-5f);
    h[base + tid]       = d0 * inv * g[tid]       + b[tid];
    h[base + tid + 256] = d1 * inv * g[tid + 256] + b[tid + 256];
    h[base + tid + 512] = d2 * inv * g[tid + 512] + b[tid + 512];
}

// ---------------- host orchestration ----------------
extern "C" void kernel_launch(void* const* d_in, const int* in_sizes, int n_in,
                              void* d_out, int out_size)
{
    const int*   x         = (const int*)  d_in[0];
    const float* condition = (const float*)d_in[1];
    const float* mems      = (const float*)d_in[2];
    const float* emb       = (const float*)d_in[3];
    const float* qkv_w     = (const float*)d_in[4];
    const float* r_net_w   = (const float*)d_in[5];
    const float* o_w       = (const float*)d_in[6];
    const float* ln1_g     = (const float*)d_in[7];
    const float* ln1_b     = (const float*)d_in[8];
    const float* w1        = (const float*)d_in[9];
    const float* b1        = (const float*)d_in[10];
    const float* w2        = (const float*)d_in[11];
    const float* b2        = (const float*)d_in[12];
    const float* ln2_g     = (const float*)d_in[13];
    const float* ln2_b     = (const float*)d_in[14];
    const float* r_w_bias  = (const float*)d_in[15];
    const float* r_r_bias  = (const float*)d_in[16];
    const float* proj_w    = (const float*)d_in[17];
    const float* proj_b    = (const float*)d_in[18];
    float* out = (float*)d_out;

    float *h, *r, *heads, *rk, *ac, *bd, *av, *ff;
    cudaGetSymbolAddress((void**)&h,     g_h);
    cudaGetSymbolAddress((void**)&r,     g_r);
    cudaGetSymbolAddress((void**)&heads, g_heads);
    cudaGetSymbolAddress((void**)&rk,    g_rk);
    cudaGetSymbolAddress((void**)&ac,    g_ac);
    cudaGetSymbolAddress((void**)&bd,    g_bd);
    cudaGetSymbolAddress((void**)&av,    g_av);
    cudaGetSymbolAddress((void**)&ff,    g_ff);

    embed_kernel<<<(QB * DMODEL + 255) / 256, 256>>>(x, emb);
    posemb_kernel<<<(KLEN * DMODEL + 255) / 256, 256>>>();

    for (int l = 0; l < NLAYER; l++) {
        const float* W = qkv_w + (size_t)l * DMODEL * TND;

        // qkv projection of the concatenated sequence (condition | mems[l] | h).
        // condition & mems rows only need k,v (q of those rows is never read).
        gemm_nn<<<dim3(24, 2), 256>>>(condition, DMODEL, W + ND, TND,
                                      heads + ND, TND,
                                      CLEN * BSZ, 2 * ND, DMODEL, nullptr, 0);
        gemm_nn<<<dim3(24, 32), 256>>>(mems + (size_t)l * MLEN * BSZ * DMODEL, DMODEL,
                                       W + ND, TND,
                                       heads + (size_t)CLEN * BSZ * TND + ND, TND,
                                       MLEN * BSZ, 2 * ND, DMODEL, nullptr, 0);
        gemm_nn<<<dim3(36, 32), 256>>>(h, DMODEL, W, TND,
                                       heads + (size_t)(CLEN + MLEN) * BSZ * TND, TND,
                                       QB, TND, DMODEL, nullptr, 0);

        // rk = r @ r_net_w[l]   [KLEN, 768]
        gemm_nn<<<dim3(12, 17), 256>>>(r, DMODEL, r_net_w + (size_t)l * DMODEL * ND, ND,
                                       rk, ND, KLEN, ND, DMODEL, nullptr, 0);

        const float* qbase = heads + (size_t)(CLEN + MLEN) * BSZ * TND;  // q of last QLEN positions
        // AC[z,i,j] = (q + r_w_bias) . k
        gemm_nt_batched<<<dim3(17, 8, NBATCH), 256>>>(
            qbase, BSZ * TND, TND, DH, r_w_bias,
            heads + ND, BSZ * TND, TND, DH,
            ac, QLEN, KLEN, DH);
        // BD_raw[z,i,j] = (q + r_r_bias) . rk
        gemm_nt_batched<<<dim3(17, 8, NBATCH), 256>>>(
            qbase, BSZ * TND, TND, DH, r_r_bias,
            rk, ND, 0, DH,
            bd, QLEN, KLEN, DH);

        softmax_kernel<<<dim3(QLEN, NBATCH), 256>>>();

        // av[i,b,n,:] = prob[z,i,:] @ v
        gemm_nn_batched<<<dim3(1, 8, NBATCH), 256>>>(
            ac, KLEN, QLEN * KLEN,
            heads + 2 * ND, BSZ * TND, TND, DH,
            av, BSZ * DMODEL, DMODEL, DH,
            QLEN, DH, KLEN);

        // attention output projection, residual + LN
        gemm_nn<<<dim3(12, 32), 256>>>(av, DMODEL, o_w + (size_t)l * ND * DMODEL, DMODEL,
                                       ff, DMODEL, QB, DMODEL, ND, nullptr, 0);
        add_ln_kernel<<<QB, 256>>>(h, ff, ln1_g + l * DMODEL, ln1_b + l * DMODEL);

        // FFN
        gemm_nn<<<dim3(48, 32), 256>>>(h, DMODEL, w1 + (size_t)l * DMODEL * DFF, DFF,
                                       ff, DFF, QB, DFF, DMODEL, b1 + (size_t)l * DFF, 1);
        gemm_nn<<<dim3(12, 32), 256>>>(ff, DFF, w2 + (size_t)l * DFF * DMODEL, DMODEL,
                                       av, DMODEL, QB, DMODEL, DFF, b2 + (size_t)l * DMODEL, 0);
        add_ln_kernel<<<QB, 256>>>(h, av, ln2_g + l * DMODEL, ln2_b + l * DMODEL);
    }

    // final projection to vocab
    gemm_nn<<<dim3((NV + 63) / 64, 32), 256>>>(h, DMODEL, proj_w, NV,
                                               out, NV, QB, NV, DMODEL, proj_b, 0);
}

// round 3
// speedup vs baseline: 1.7012x; 1.7012x over previous
#include <cuda_runtime.h>
#include <math.h>

#define NLAYER 12
#define NH 12
#define DH 64
#define DMODEL 768
#define DFF 3072
#define NV 10000
#define QLEN 512
#define MLEN 512
#define CLEN 32
#define BSZ 4
#define KLEN 1056               // CLEN + MLEN + QLEN
#define QB (QLEN*BSZ)           // 2048
#define KB (KLEN*BSZ)           // 4224
#define TND (3*NH*DH)           // 2304
#define ND (NH*DH)              // 768
#define NBATCH (BSZ*NH)         // 48

// ---------------- scratch (device globals; no allocation) ----------------
__device__ float g_h[QB*DMODEL];
__device__ float g_r[KLEN*DMODEL];
__device__ float g_heads[(size_t)KB*TND];
__device__ float g_rk[KLEN*DMODEL];
__device__ float g_ac[(size_t)NBATCH*QLEN*KLEN];
__device__ float g_bd[(size_t)NBATCH*QLEN*KLEN];
__device__ float g_av[QB*DMODEL];
__device__ float g_ff[(size_t)QB*DFF];

// ---------------- small helpers ----------------
__device__ __forceinline__ float warp_sum(float v) {
    #pragma unroll
    for (int o = 16; o; o >>= 1) v += __shfl_xor_sync(0xffffffffu, v, o);
    return v;
}
__device__ __forceinline__ float warp_max(float v) {
    #pragma unroll
    for (int o = 16; o; o >>= 1) v = fmaxf(v, __shfl_xor_sync(0xffffffffu, v, o));
    return v;
}
__device__ __forceinline__ float block_sum(float v, float* red) {
    v = warp_sum(v);
    __syncthreads();
    if ((threadIdx.x & 31) == 0) red[threadIdx.x >> 5] = v;
    __syncthreads();
    float r = 0.f;
    #pragma unroll
    for (int k = 0; k < 8; k++) r += red[k];
    return r;
}

// ---------------- embedding ----------------
__global__ void embed_kernel(const int* __restrict__ x, const float* __restrict__ emb) {
    int idx = blockIdx.x * 256 + threadIdx.x;
    if (idx >= QB * DMODEL) return;
    int row = idx / DMODEL, d = idx % DMODEL;
    int tok = x[row];
    g_h[idx] = emb[(size_t)tok * DMODEL + d] * sqrtf(768.0f);
}

// ---------------- sinusoidal relative position embedding ----------------
__global__ void posemb_kernel() {
    int idx = blockIdx.x * 256 + threadIdx.x;
    if (idx >= KLEN * DMODEL) return;
    int p = idx / DMODEL, d = idx % DMODEL;
    float pos = (float)(KLEN - 1 - p);
    int dd = (d < 384) ? d : d - 384;
    float inv = 1.0f / powf(10000.0f, (float)(2 * dd) / 768.0f);
    float s = pos * inv;
    g_r[idx] = (d < 384) ? sinf(s) : cosf(s);
}

// ---------------- big NN GEMM: 128x128 tile, 8x8 micro, double-buffered ----------------
// C[M,N] = A[M,K] @ B[K,N] (+bias)(+relu). K must be a multiple of 16, N a multiple of 4.
__global__ void __launch_bounds__(256, 2)
gemm128(const float* __restrict__ A, int lda,
        const float* __restrict__ B, int ldb,
        float* __restrict__ C, int ldc,
        int M, int N, int K,
        const float* __restrict__ bias, int relu)
{
    __shared__ float As[2][16][132];   // padded to kill transpose-store conflicts
    __shared__ float Bs[2][16][128];
    const int tid = threadIdx.x;
    const int row0 = blockIdx.y * 128, col0 = blockIdx.x * 128;
    const int ar  = tid >> 2;          // 0..63  (A staging row)
    const int acl = (tid & 3) << 2;    // 0,4,8,12 (A staging k-col)
    const int br  = tid >> 5;          // 0..7   (B staging k-row)
    const int bcl = (tid & 31) << 2;   // 0..124 (B staging col)
    const int ty4 = (tid >> 4) << 2;
    const int tx4 = (tid & 15) << 2;

    const bool aval0 = (row0 + ar) < M;
    const bool aval1 = (row0 + ar + 64) < M;
    const bool bval  = (col0 + bcl) < N;
    const float* Ap0 = A + (size_t)(row0 + ar) * lda + acl;
    const float* Ap1 = A + (size_t)(row0 + ar + 64) * lda + acl;
    const float* Bp0 = B + (size_t)br * ldb + col0 + bcl;
    const float* Bp1 = B + (size_t)(br + 8) * ldb + col0 + bcl;

    float acc[8][8] = {};
    const int KT = K >> 4;
    const float4 z4 = make_float4(0.f, 0.f, 0.f, 0.f);
    float4 fa0, fa1, fb0, fb1;

#define FETCH(k0) do { \
        fa0 = aval0 ? *(const float4*)(Ap0 + (k0)) : z4; \
        fa1 = aval1 ? *(const float4*)(Ap1 + (k0)) : z4; \
        fb0 = bval  ? *(const float4*)(Bp0 + (size_t)(k0) * ldb) : z4; \
        fb1 = bval  ? *(const float4*)(Bp1 + (size_t)(k0) * ldb) : z4; \
    } while (0)
#define STAGE(bf) do { \
        As[bf][acl+0][ar] = fa0.x; As[bf][acl+1][ar] = fa0.y; \
        As[bf][acl+2][ar] = fa0.z; As[bf][acl+3][ar] = fa0.w; \
        As[bf][acl+0][ar+64] = fa1.x; As[bf][acl+1][ar+64] = fa1.y; \
        As[bf][acl+2][ar+64] = fa1.z; As[bf][acl+3][ar+64] = fa1.w; \
        *(float4*)&Bs[bf][br][bcl]     = fb0; \
        *(float4*)&Bs[bf][br + 8][bcl] = fb1; \
    } while (0)

    FETCH(0); STAGE(0); __syncthreads();

    for (int kt = 0; kt < KT; kt++) {
        int buf = kt & 1;
        if (kt + 1 < KT) FETCH((kt + 1) << 4);
        #pragma unroll
        for (int k = 0; k < 16; k++) {
            float4 xa0 = *(const float4*)&As[buf][k][ty4];
            float4 xa1 = *(const float4*)&As[buf][k][ty4 + 64];
            float4 xb0 = *(const float4*)&Bs[buf][k][tx4];
            float4 xb1 = *(const float4*)&Bs[buf][k][tx4 + 64];
            float av8[8] = {xa0.x, xa0.y, xa0.z, xa0.w, xa1.x, xa1.y, xa1.z, xa1.w};
            float bv8[8] = {xb0.x, xb0.y, xb0.z, xb0.w, xb1.x, xb1.y, xb1.z, xb1.w};
            #pragma unroll
            for (int i = 0; i < 8; i++)
                #pragma unroll
                for (int j = 0; j < 8; j++) acc[i][j] += av8[i] * bv8[j];
        }
        if (kt + 1 < KT) { STAGE(buf ^ 1); __syncthreads(); }
    }
#undef FETCH
#undef STAGE

    #pragma unroll
    for (int i = 0; i < 8; i++) {
        int r = row0 + ty4 + ((i < 4) ? i : 60 + i);   // ty4 + i  or  ty4 + 64 + (i-4)
        if (r >= M) continue;
        #pragma unroll
        for (int j = 0; j < 8; j++) {
            int c = col0 + tx4 + ((j < 4) ? j : 60 + j);
            if (c >= N) continue;
            float v = acc[i][j];
            if (bias) v += bias[c];
            if (relu) v = fmaxf(v, 0.f);
            C[(size_t)r * ldc + c] = v;
        }
    }
}

// ---------------- fused attention scores: AC = (q+rwb)@k^T, BD = (q+rrb)@rk^T ----------------
// One block: 64 q-rows x 64 key-cols for one (b,n). q tile staged once, biases folded in.
__global__ void __launch_bounds__(256)
attn_scores(const float* __restrict__ heads, const float* __restrict__ rk,
            const float* __restrict__ rwb, const float* __restrict__ rrb,
            float* __restrict__ ac, float* __restrict__ bd)
{
    const int z = blockIdx.z, bb = z / NH, nn = z % NH;
    const float* q  = heads + (size_t)(CLEN + MLEN) * BSZ * TND + (size_t)bb * TND + nn * DH;
    const float* kk = heads + ND + (size_t)bb * TND + nn * DH;
    const float* rr = rk + nn * DH;
    const float* wb = rwb + nn * DH;
    const float* rb = rrb + nn * DH;
    const int row0 = blockIdx.y * 64, col0 = blockIdx.x * 64;

    __shared__ float Qw[32][68], Qr[32][68], Ks[32][68], Rs[32][68];
    const int tid = threadIdx.x;
    const int tx4 = (tid & 15) << 2, ty4 = (tid >> 4) << 2;
    float acc1[4][4] = {}, acc2[4][4] = {};

    for (int k0 = 0; k0 < DH; k0 += 32) {
        #pragma unroll
        for (int s = 0; s < 2; s++) {
            int idx = tid * 2 + s;              // 0..511
            int m = idx >> 3, c4 = (idx & 7) << 2;
            // q rows (always valid: QLEN multiple of 64)
            float4 qv = *(const float4*)(q + (size_t)(row0 + m) * (BSZ * TND) + k0 + c4);
            Qw[c4+0][m] = qv.x + wb[k0+c4+0]; Qw[c4+1][m] = qv.y + wb[k0+c4+1];
            Qw[c4+2][m] = qv.z + wb[k0+c4+2]; Qw[c4+3][m] = qv.w + wb[k0+c4+3];
            Qr[c4+0][m] = qv.x + rb[k0+c4+0]; Qr[c4+1][m] = qv.y + rb[k0+c4+1];
            Qr[c4+2][m] = qv.z + rb[k0+c4+2]; Qr[c4+3][m] = qv.w + rb[k0+c4+3];
            // key / rk cols (guard j < KLEN)
            int jj = col0 + m;
            float4 kv = make_float4(0,0,0,0), rv = make_float4(0,0,0,0);
            if (jj < KLEN) {
                kv = *(const float4*)(kk + (size_t)jj * (BSZ * TND) + k0 + c4);
                rv = *(const float4*)(rr + (size_t)jj * ND + k0 + c4);
            }
            Ks[c4+0][m] = kv.x; Ks[c4+1][m] = kv.y; Ks[c4+2][m] = kv.z; Ks[c4+3][m] = kv.w;
            Rs[c4+0][m] = rv.x; Rs[c4+1][m] = rv.y; Rs[c4+2][m] = rv.z; Rs[c4+3][m] = rv.w;
        }
        __syncthreads();
        #pragma unroll
        for (int k = 0; k < 32; k++) {
            float4 qa = *(const float4*)&Qw[k][ty4];
            float4 qb = *(const float4*)&Qr[k][ty4];
            float4 kv = *(const float4*)&Ks[k][tx4];
            float4 rv = *(const float4*)&Rs[k][tx4];
            float a1[4] = {qa.x, qa.y, qa.z, qa.w};
            float a2[4] = {qb.x, qb.y, qb.z, qb.w};
            float b1[4] = {kv.x, kv.y, kv.z, kv.w};
            float b2[4] = {rv.x, rv.y, rv.z, rv.w};
            #pragma unroll
            for (int i = 0; i < 4; i++)
                #pragma unroll
                for (int j = 0; j < 4; j++) {
                    acc1[i][j] += a1[i] * b1[j];
                    acc2[i][j] += a2[i] * b2[j];
                }
        }
        __syncthreads();
    }

    #pragma unroll
    for (int i = 0; i < 4; i++) {
        size_t rbase = ((size_t)z * QLEN + row0 + ty4 + i) * KLEN;
        #pragma unroll
        for (int j = 0; j < 4; j++) {
            int c = col0 + tx4 + j;
            if (c >= KLEN) continue;
            ac[rbase + c] = acc1[i][j];
            bd[rbase + c] = acc2[i][j];
        }
    }
}

// ---------------- av = prob @ v per (b,n): [512 x 1056] @ [1056 x 64] ----------------
__global__ void __launch_bounds__(256)
attn_av(const float* __restrict__ prob, const float* __restrict__ heads,
        float* __restrict__ av)
{
    const int z = blockIdx.z, bb = z / NH, nn = z % NH;
    const float* P = prob + (size_t)z * QLEN * KLEN;
    const float* V = heads + 2 * ND + (size_t)bb * TND + nn * DH;
    float* O = av + (size_t)bb * DMODEL + nn * DH;
    const int row0 = blockIdx.y * 64;

    __shared__ float Ps[32][68];  // [k][i]
    __shared__ float Vs[32][68];  // [k][d]
    const int tid = threadIdx.x;
    const int tx4 = (tid & 15) << 2, ty4 = (tid >> 4) << 2;
    float acc[4][4] = {};

    for (int k0 = 0; k0 < KLEN; k0 += 32) {
        #pragma unroll
        for (int s = 0; s < 2; s++) {
            int idx = tid * 2 + s;
            int m = idx >> 3, c4 = (idx & 7) << 2;
            float4 pv = *(const float4*)(P + (size_t)(row0 + m) * KLEN + k0 + c4);
            Ps[c4+0][m] = pv.x; Ps[c4+1][m] = pv.y; Ps[c4+2][m] = pv.z; Ps[c4+3][m] = pv.w;
            int kk_ = idx >> 4, c4v = (idx & 15) << 2;
            float4 vv = *(const float4*)(V + (size_t)(k0 + kk_) * (BSZ * TND) + c4v);
            *(float4*)&Vs[kk_][c4v] = vv;
        }
        __syncthreads();
        #pragma unroll
        for (int k = 0; k < 32; k++) {
            float4 pa = *(const float4*)&Ps[k][ty4];
            float4 vb = *(const float4*)&Vs[k][tx4];
            float a[4] = {pa.x, pa.y, pa.z, pa.w};
            float b[4] = {vb.x, vb.y, vb.z, vb.w};
            #pragma unroll
            for (int i = 0; i < 4; i++)
                #pragma unroll
                for (int j = 0; j < 4; j++) acc[i][j] += a[i] * b[j];
        }
        __syncthreads();
    }

    #pragma unroll
    for (int i = 0; i < 4; i++)
        #pragma unroll
        for (int j = 0; j < 4; j++)
            O[(size_t)(row0 + ty4 + i) * (BSZ * DMODEL) + tx4 + j] = acc[i][j];
}

// ---------------- masked softmax with rel-shift folded in ----------------
__global__ void __launch_bounds__(256) softmax_kernel() {
    int i = blockIdx.x, z = blockIdx.y;
    float* row = g_ac + ((size_t)z * QLEN + i) * KLEN;
    const float* bdrow = g_bd + ((size_t)z * QLEN + i) * KLEN;
    int jmax = i + CLEN + MLEN;      // inclusive
    __shared__ float s[KLEN];
    __shared__ float red[8];
    int tid = threadIdx.x;
    float lmax = -3.0e38f;
    for (int j = tid; j <= jmax; j += 256) {
        float v = (row[j] + bdrow[j + QLEN - 1 - i]) * 0.125f;
        s[j] = v;
        lmax = fmaxf(lmax, v);
    }
    lmax = warp_max(lmax);
    __syncthreads();
    if ((tid & 31) == 0) red[tid >> 5] = lmax;
    __syncthreads();
    float m = red[0];
    #pragma unroll
    for (int k = 1; k < 8; k++) m = fmaxf(m, red[k]);
    float lsum = 0.f;
    for (int j = tid; j <= jmax; j += 256) {
        float e = expf(s[j] - m);
        s[j] = e;
        lsum += e;
    }
    float total = block_sum(lsum, red);
    float inv = 1.0f / total;
    __syncthreads();
    for (int j = tid; j < KLEN; j += 256)
        row[j] = (j <= jmax) ? s[j] * inv : 0.0f;
}

// ---------------- h = LayerNorm(h + res) * g + b ----------------
__global__ void __launch_bounds__(256)
add_ln_kernel(float* __restrict__ h, const float* __restrict__ res,
              const float* __restrict__ g, const float* __restrict__ b)
{
    __shared__ float red[8];
    int row = blockIdx.x, tid = threadIdx.x;
    size_t base = (size_t)row * DMODEL;
    float x0 = h[base + tid]       + res[base + tid];
    float x1 = h[base + tid + 256] + res[base + tid + 256];
    float x2 = h[base + tid + 512] + res[base + tid + 512];
    float S = block_sum(x0 + x1 + x2, red);
    float mean = S * (1.0f / 768.0f);
    float d0 = x0 - mean, d1 = x1 - mean, d2 = x2 - mean;
    float V = block_sum(d0 * d0 + d1 * d1 + d2 * d2, red);
    float inv = rsqrtf(V * (1.0f / 768.0f) + 1e-5f);
    h[base + tid]       = d0 * inv * g[tid]       + b[tid];
    h[base + tid + 256] = d1 * inv * g[tid + 256] + b[tid + 256];
    h[base + tid + 512] = d2 * inv * g[tid + 512] + b[tid + 512];
}

// ---------------- host orchestration ----------------
extern "C" void kernel_launch(void* const* d_in, const int* in_sizes, int n_in,
                              void* d_out, int out_size)
{
    const int*   x         = (const int*)  d_in[0];
    const float* condition = (const float*)d_in[1];
    const float* mems      = (const float*)d_in[2];
    const float* emb       = (const float*)d_in[3];
    const float* qkv_w     = (const float*)d_in[4];
    const float* r_net_w   = (const float*)d_in[5];
    const float* o_w       = (const float*)d_in[6];
    const float* ln1_g     = (const float*)d_in[7];
    const float* ln1_b     = (const float*)d_in[8];
    const float* w1        = (const float*)d_in[9];
    const float* b1        = (const float*)d_in[10];
    const float* w2        = (const float*)d_in[11];
    const float* b2        = (const float*)d_in[12];
    const float* ln2_g     = (const float*)d_in[13];
    const float* ln2_b     = (const float*)d_in[14];
    const float* r_w_bias  = (const float*)d_in[15];
    const float* r_r_bias  = (const float*)d_in[16];
    const float* proj_w    = (const float*)d_in[17];
    const float* proj_b    = (const float*)d_in[18];
    float* out = (float*)d_out;

    float *h, *r, *heads, *rk, *ac, *bd, *av, *ff;
    cudaGetSymbolAddress((void**)&h,     g_h);
    cudaGetSymbolAddress((void**)&r,     g_r);
    cudaGetSymbolAddress((void**)&heads, g_heads);
    cudaGetSymbolAddress((void**)&rk,    g_rk);
    cudaGetSymbolAddress((void**)&ac,    g_ac);
    cudaGetSymbolAddress((void**)&bd,    g_bd);
    cudaGetSymbolAddress((void**)&av,    g_av);
    cudaGetSymbolAddress((void**)&ff,    g_ff);

    embed_kernel<<<(QB * DMODEL + 255) / 256, 256>>>(x, emb);
    posemb_kernel<<<(KLEN * DMODEL + 255) / 256, 256>>>();

    for (int l = 0; l < NLAYER; l++) {
        const float* W = qkv_w + (size_t)l * DMODEL * TND;

        // qkv projection of (condition | mems[l] | h). cond/mems rows only need k,v.
        gemm128<<<dim3(12, 1), 256>>>(condition, DMODEL, W + ND, TND,
                                      heads + ND, TND,
                                      CLEN * BSZ, 2 * ND, DMODEL, nullptr, 0);
        gemm128<<<dim3(12, 16), 256>>>(mems + (size_t)l * MLEN * BSZ * DMODEL, DMODEL,
                                       W + ND, TND,
                                       heads + (size_t)CLEN * BSZ * TND + ND, TND,
                                       MLEN * BSZ, 2 * ND, DMODEL, nullptr, 0);
        gemm128<<<dim3(18, 16), 256>>>(h, DMODEL, W, TND,
                                       heads + (size_t)(CLEN + MLEN) * BSZ * TND, TND,
                                       QB, TND, DMODEL, nullptr, 0);

        // rk = r @ r_net_w[l]   [KLEN, 768]
        gemm128<<<dim3(6, 9), 256>>>(r, DMODEL, r_net_w + (size_t)l * DMODEL * ND, ND,
                                     rk, ND, KLEN, ND, DMODEL, nullptr, 0);

        // fused AC / BD score GEMMs
        attn_scores<<<dim3(17, 8, NBATCH), 256>>>(heads, rk, r_w_bias, r_r_bias, ac, bd);

        softmax_kernel<<<dim3(QLEN, NBATCH), 256>>>();

        // av[i,b,n,:] = prob[z,i,:] @ v
        attn_av<<<dim3(1, 8, NBATCH), 256>>>(ac, heads, av);

        // attention output projection, residual + LN
        gemm128<<<dim3(6, 16), 256>>>(av, DMODEL, o_w + (size_t)l * ND * DMODEL, DMODEL,
                                      ff, DMODEL, QB, DMODEL, ND, nullptr, 0);
        add_ln_kernel<<<QB, 256>>>(h, ff, ln1_g + l * DMODEL, ln1_b + l * DMODEL);

        // FFN
        gemm128<<<dim3(24, 16), 256>>>(h, DMODEL, w1 + (size_t)l * DMODEL * DFF, DFF,
                                       ff, DFF, QB, DFF, DMODEL, b1 + (size_t)l * DFF, 1);
        gemm128<<<dim3(6, 16), 256>>>(ff, DFF, w2 + (size_t)l * DFF * DMODEL, DMODEL,
                                      av, DMODEL, QB, DMODEL, DFF, b2 + (size_t)l * DMODEL, 0);
        add_ln_kernel<<<QB, 256>>>(h, av, ln2_g + l * DMODEL, ln2_b + l * DMODEL);
    }

    // final projection to vocab
    gemm128<<<dim3((NV + 127) / 128, 16), 256>>>(h, DMODEL, proj_w, NV,
                                                 out, NV, QB, NV, DMODEL, proj_b, 0);
}